// round 8
// baseline (speedup 1.0000x reference)
#include <cuda_runtime.h>
#include <cuda_bf16.h>
#include <math.h>

#define BB 128
#define PP 8732
#define CC 21
#define NO 16

// ---- scratch (no allocations allowed) ----
__device__ float         g_bto[BB * PP];      // best truth overlap per (b,p)
__device__ unsigned char g_bti[BB * PP];      // best truth idx per (b,p)
__device__ unsigned char g_conf[BB * PP];     // conf target (0..20)
__device__ float         g_scores[BB * PP];   // mining score (0 at positives)
__device__ int           g_numpos[BB];
__device__ float         g_loss_l;
__device__ float         g_loss_c;

__global__ void k_init() { g_loss_l = 0.f; g_loss_c = 0.f; }

// ---------------------------------------------------------------------------
// Kernel 1: matching + localization loss. One block per batch element.
// ---------------------------------------------------------------------------
__global__ void __launch_bounds__(256) k_match(const float* __restrict__ loc,
                                               const float* __restrict__ priors,
                                               const float* __restrict__ truths,
                                               const int*   __restrict__ labels)
{
    const int b = blockIdx.x;
    const int tid = threadIdx.x;

    __shared__ float st[NO][4];
    __shared__ int   sl[NO];
    __shared__ unsigned long long sbp[NO];   // packed (iou_bits<<32)|(~p)
    __shared__ int   sbpi[NO];               // best prior idx per truth
    __shared__ float wf[8];
    __shared__ int   wi[8];

    if (tid < NO) {
        const float* t = truths + (b * NO + tid) * 4;
        st[tid][0] = t[0]; st[tid][1] = t[1]; st[tid][2] = t[2]; st[tid][3] = t[3];
        sl[tid]  = labels[b * NO + tid];
        sbp[tid] = 0ull;
    }
    __syncthreads();

    // ---- pass 1: per-prior best truth, per-truth best prior (local) ----
    unsigned long long key[NO];
#pragma unroll
    for (int j = 0; j < NO; j++) key[j] = 0ull;

    for (int p = tid; p < PP; p += 256) {
        float4 pr = ((const float4*)priors)[p];
        float px1 = pr.x - pr.z * 0.5f, py1 = pr.y - pr.w * 0.5f;
        float px2 = pr.x + pr.z * 0.5f, py2 = pr.y + pr.w * 0.5f;
        float area_p = (px2 - px1) * (py2 - py1);
        float bov = -1.f; int bj = 0;
#pragma unroll
        for (int j = 0; j < NO; j++) {
            float tx1 = st[j][0], ty1 = st[j][1], tx2 = st[j][2], ty2 = st[j][3];
            float ix = fmaxf(fminf(tx2, px2) - fmaxf(tx1, px1), 0.f);
            float iy = fmaxf(fminf(ty2, py2) - fmaxf(ty1, py1), 0.f);
            float inter = ix * iy;
            float at = (tx2 - tx1) * (ty2 - ty1);
            float iou = inter / (at + area_p - inter);
            if (iou > bov) { bov = iou; bj = j; }   // first-max over truths
            unsigned long long cand =
                ((unsigned long long)__float_as_uint(iou) << 32) |
                (unsigned long long)(0xFFFFFFFFu - (unsigned)p);  // smaller p wins ties
            key[j] = (cand > key[j]) ? cand : key[j];
        }
        g_bto[b * PP + p] = bov;
        g_bti[b * PP + p] = (unsigned char)bj;
    }
#pragma unroll
    for (int j = 0; j < NO; j++) atomicMax(&sbp[j], key[j]);
    __syncthreads();
    if (tid < NO)
        sbpi[tid] = (int)(0xFFFFFFFFu - (unsigned)(sbp[tid] & 0xFFFFFFFFull));
    __syncthreads();

    // ---- pass 2: forced matches, conf targets, encode + smooth-L1 ----
    float lsum = 0.f; int npos = 0;
    for (int p = tid; p < PP; p += 256) {
        float ov = g_bto[b * PP + p];
        int   j  = g_bti[b * PP + p];
        int forced = -1;
#pragma unroll
        for (int jj = 0; jj < NO; jj++) if (sbpi[jj] == p) forced = jj; // scatter-max j
        if (forced >= 0) { j = forced; ov = 2.f; }
        int conf = (ov < 0.5f) ? 0 : sl[j];
        g_conf[b * PP + p] = (unsigned char)conf;
        if (conf > 0) {
            npos++;
            float4 pr = ((const float4*)priors)[p];
            float tx1 = st[j][0], ty1 = st[j][1], tx2 = st[j][2], ty2 = st[j][3];
            float gx = ((tx1 + tx2) * 0.5f - pr.x) / (0.1f * pr.z);
            float gy = ((ty1 + ty2) * 0.5f - pr.y) / (0.1f * pr.w);
            float gw = logf((tx2 - tx1) / pr.z) * 5.0f;   // 1/0.2
            float gh = logf((ty2 - ty1) / pr.w) * 5.0f;
            float4 ld = ((const float4*)loc)[b * PP + p];
            float d;
            d = fabsf(ld.x - gx); lsum += (d < 1.f) ? 0.5f * d * d : d - 0.5f;
            d = fabsf(ld.y - gy); lsum += (d < 1.f) ? 0.5f * d * d : d - 0.5f;
            d = fabsf(ld.z - gw); lsum += (d < 1.f) ? 0.5f * d * d : d - 0.5f;
            d = fabsf(ld.w - gh); lsum += (d < 1.f) ? 0.5f * d * d : d - 0.5f;
        }
    }

    // block reduce
    for (int o = 16; o > 0; o >>= 1) {
        lsum += __shfl_down_sync(0xffffffffu, lsum, o);
        npos += __shfl_down_sync(0xffffffffu, npos, o);
    }
    if ((tid & 31) == 0) { wf[tid >> 5] = lsum; wi[tid >> 5] = npos; }
    __syncthreads();
    if (tid == 0) {
        float L = 0.f; int N = 0;
        for (int i = 0; i < 8; i++) { L += wf[i]; N += wi[i]; }
        g_numpos[b] = N;
        atomicAdd(&g_loss_l, L);
    }
}

// ---------------------------------------------------------------------------
// Kernel 2: per-(b,p) score s = lse_row - x[gt]; positives summed directly,
// scores zeroed at positives (excluded from mining top-k but present).
// Coalesced load via shared staging (21 floats/row).
// ---------------------------------------------------------------------------
__global__ void __launch_bounds__(256) k_scores(const float* __restrict__ conf)
{
    __shared__ float sh[256 * CC];   // 21504 B
    __shared__ float wf[8];
    const int warp = threadIdx.x >> 5, lane = threadIdx.x & 31;
    const int base_row = blockIdx.x * 256 + warp * 32;

    const float* src = conf + (size_t)base_row * CC;
    float* dst = sh + warp * (32 * CC);
#pragma unroll
    for (int t = 0; t < CC; t++) dst[lane + t * 32] = src[lane + t * 32];
    __syncwarp();

    const float* my = dst + lane * CC;   // row stride 21 -> bank-conflict-free
    float m = my[0];
#pragma unroll
    for (int c = 1; c < CC; c++) m = fmaxf(m, my[c]);
    float s = 0.f;
#pragma unroll
    for (int c = 0; c < CC; c++) s += __expf(my[c] - m);
    float lse = __logf(s) + m;

    const int r = base_row + lane;
    const int gt = g_conf[r];
    float val = lse - my[gt];
    float posloss = 0.f;
    if (gt > 0) { posloss = val; val = 0.f; }
    g_scores[r] = val;

    // block reduce positive CE into g_loss_c
    for (int o = 16; o > 0; o >>= 1)
        posloss += __shfl_down_sync(0xffffffffu, posloss, o);
    if (lane == 0) wf[warp] = posloss;
    __syncthreads();
    if (threadIdx.x == 0) {
        float L = 0.f;
        for (int i = 0; i < 8; i++) L += wf[i];
        atomicAdd(&g_loss_c, L);
    }
}

// ---------------------------------------------------------------------------
// Kernel 3: per-batch top-k sum of mining scores via 31-step radix select on
// IEEE bit patterns (all scores >= 0). One block per batch, scores in shared.
// ---------------------------------------------------------------------------
__global__ void __launch_bounds__(256) k_select()
{
    __shared__ unsigned int sb[PP];       // 34928 B
    __shared__ int   wi[8];
    __shared__ float wf[8];
    __shared__ int   s_total;

    const int b = blockIdx.x, tid = threadIdx.x;
    for (int p = tid; p < PP; p += 256)
        sb[p] = __float_as_uint(g_scores[b * PP + p]);
    __syncthreads();

    const int np = g_numpos[b];
    int k = 3 * np; if (k > PP - 1) k = PP - 1;
    if (k <= 0) return;  // uniform across block

    unsigned prefix = 0;
    for (int bit = 30; bit >= 0; bit--) {
        unsigned cand = prefix | (1u << bit);
        int cnt = 0;
        for (int p = tid; p < PP; p += 256) cnt += (sb[p] >= cand);
        for (int o = 16; o > 0; o >>= 1)
            cnt += __shfl_down_sync(0xffffffffu, cnt, o);
        if ((tid & 31) == 0) wi[tid >> 5] = cnt;
        __syncthreads();
        if (tid == 0) {
            int t = 0;
            for (int i = 0; i < 8; i++) t += wi[i];
            s_total = t;
        }
        __syncthreads();
        if (s_total >= k) prefix = cand;
        __syncthreads();
    }
    const unsigned kth_bits = prefix;             // k-th largest value
    const float kth = __uint_as_float(kth_bits);

    int cgt = 0; float sgt = 0.f;
    for (int p = tid; p < PP; p += 256) {
        unsigned v = sb[p];
        if (v > kth_bits) { cgt++; sgt += __uint_as_float(v); }
    }
    for (int o = 16; o > 0; o >>= 1) {
        cgt += __shfl_down_sync(0xffffffffu, cgt, o);
        sgt += __shfl_down_sync(0xffffffffu, sgt, o);
    }
    if ((tid & 31) == 0) { wi[tid >> 5] = cgt; wf[tid >> 5] = sgt; }
    __syncthreads();
    if (tid == 0) {
        int   C = 0; float S = 0.f;
        for (int i = 0; i < 8; i++) { C += wi[i]; S += wf[i]; }
        atomicAdd(&g_loss_c, S + (float)(k - C) * kth);
    }
}

// ---------------------------------------------------------------------------
// Kernel 4: finalize.
// ---------------------------------------------------------------------------
__global__ void __launch_bounds__(128) k_final(float* __restrict__ out)
{
    __shared__ int s[128];
    const int tid = threadIdx.x;
    s[tid] = g_numpos[tid];
    __syncthreads();
    for (int o = 64; o > 0; o >>= 1) {
        if (tid < o) s[tid] += s[tid + o];
        __syncthreads();
    }
    if (tid == 0) {
        float N = fmaxf((float)s[0], 1.0f);
        out[0] = g_loss_l / N;
        out[1] = g_loss_c / N;
    }
}

extern "C" void kernel_launch(void* const* d_in, const int* in_sizes, int n_in,
                              void* d_out, int out_size)
{
    const float* loc    = (const float*)d_in[0];  // [B,P,4]
    const float* conf   = (const float*)d_in[1];  // [B,P,C]
    const float* priors = (const float*)d_in[2];  // [P,4]
    const float* truths = (const float*)d_in[3];  // [B,NO,4]
    const int*   labels = (const int*)d_in[4];    // [B,NO]
    float* out = (float*)d_out;

    k_init<<<1, 1>>>();
    k_match<<<BB, 256>>>(loc, priors, truths, labels);
    k_scores<<<(BB * PP) / 256, 256>>>(conf);
    k_select<<<BB, 256>>>();
    k_final<<<1, 128>>>(out);
}